// round 1
// baseline (speedup 1.0000x reference)
#include <cuda_runtime.h>
#include <cstdint>

#define D_MODEL 1024
#define TPB 256            // threads per block; each thread owns 4 channels (1024/256*... -> tid*4)
#define TOK_PER_BLK 16

__device__ float g_A[D_MODEL];
__device__ float g_B[D_MODEL];
__device__ float g_C[D_MODEL];
__device__ int   g_is64;

// ---------------------------------------------------------------------------
// Detect whether N_tokens is int64 or int32.
// If int64 (little-endian, values in [0, 32000)), every odd 32-bit word among
// the first n_tok int32 slots is a zero high-half. If int32, those slots hold
// random token values -> OR-reduce is nonzero with overwhelming probability.
// Only reads within the first n_tok int32 words, valid for either dtype.
// ---------------------------------------------------------------------------
__global__ void detect_dtype_kernel(const int* __restrict__ p, int n_tok) {
    __shared__ int s_any;
    if (threadIdx.x == 0) s_any = 0;
    __syncthreads();
    int acc = 0;
    for (int i = 1 + 2 * (int)threadIdx.x; i < n_tok; i += 2 * (int)blockDim.x)
        acc |= p[i];
    if (acc) atomicOr(&s_any, 1);
    __syncthreads();
    if (threadIdx.x == 0) g_is64 = (s_any == 0) ? 1 : 0;
}

// ---------------------------------------------------------------------------
// Collapse Linear(12 -> D_MODEL) over the polynomial feature map into
// per-channel quadratic coefficients A, B, C.
//   feats = [t^2, t, t+1, t^2, 2t+2, -1, t^2, 0, 2t+1, t^2, 2t+1, 0]
// ---------------------------------------------------------------------------
__global__ void coeff_kernel(const float* __restrict__ W,
                             const float* __restrict__ b) {
    int d = blockIdx.x * blockDim.x + threadIdx.x;
    if (d >= D_MODEL) return;
    const float* w = W + d * 12;
    float w0 = w[0], w1 = w[1], w2 = w[2],  w3 = w[3];
    float w4 = w[4], w5 = w[5], w6 = w[6];
    float w8 = w[8], w9 = w[9], w10 = w[10];
    g_A[d] = w0 + w3 + w6 + w9;
    g_B[d] = w1 + w2 + 2.0f * (w4 + w8 + w10);
    g_C[d] = w2 + 2.0f * w4 - w5 + w8 + w10 + b[d];
}

// ---------------------------------------------------------------------------
// Main kernel: one block = 16 tokens x 1024 channels.
// Each thread holds its 4 channels' (A,B,C) in registers and streams
// STG.128 rows. Pure store-bandwidth bound.
// ---------------------------------------------------------------------------
__global__ __launch_bounds__(TPB)
void n2_embed_kernel(const void* __restrict__ ntok_raw,
                     float4* __restrict__ out,
                     int n_tok) {
    __shared__ float s_t[TOK_PER_BLK];

    const int tid  = threadIdx.x;
    const int tok0 = blockIdx.x * TOK_PER_BLK;
    const int is64 = g_is64;

    if (tid < TOK_PER_BLK) {
        int idx = tok0 + tid;
        float t = 0.0f;
        if (idx < n_tok) {
            if (is64) {
                long long v = ((const long long*)ntok_raw)[idx];
                t = (float)v;
            } else {
                int v = ((const int*)ntok_raw)[idx];
                t = (float)v;
            }
        }
        s_t[tid] = t;
    }
    __syncthreads();

    const int dbase = tid * 4;
    const float4 A = *(const float4*)&g_A[dbase];
    const float4 B = *(const float4*)&g_B[dbase];
    const float4 C = *(const float4*)&g_C[dbase];

    const int row_f4 = D_MODEL / 4;  // 256 float4 per token row

#pragma unroll
    for (int k = 0; k < TOK_PER_BLK; k++) {
        int tok = tok0 + k;
        if (tok >= n_tok) break;
        float t = s_t[k];
        float4 o;
        o.x = fmaf(fmaf(A.x, t, B.x), t, C.x);
        o.y = fmaf(fmaf(A.y, t, B.y), t, C.y);
        o.z = fmaf(fmaf(A.z, t, B.z), t, C.z);
        o.w = fmaf(fmaf(A.w, t, B.w), t, C.w);
        out[(size_t)tok * row_f4 + tid] = o;
    }
}

extern "C" void kernel_launch(void* const* d_in, const int* in_sizes, int n_in,
                              void* d_out, int out_size) {
    const void*  ntok = d_in[0];                 // int64 or int32 tokens [B*S]
    const float* W    = (const float*)d_in[1];   // [D_MODEL, 12] row-major
    const float* b    = (const float*)d_in[2];   // [D_MODEL]
    float4* out = (float4*)d_out;

    int n_tok = in_sizes[0];                     // 4 * 8192 = 32768

    detect_dtype_kernel<<<1, 256>>>((const int*)ntok, n_tok);
    coeff_kernel<<<(D_MODEL + 255) / 256, 256>>>(W, b);

    int grid = (n_tok + TOK_PER_BLK - 1) / TOK_PER_BLK;  // 2048 blocks
    n2_embed_kernel<<<grid, TPB>>>(ntok, out, n_tok);
}

// round 2
// speedup vs baseline: 1.3809x; 1.3809x over previous
#include <cuda_runtime.h>
#include <cstdint>

#define D_MODEL     1024
#define TPB         256     // each thread owns 4 contiguous channels
#define TOK_PER_BLK 64

// ---------------------------------------------------------------------------
// Single fused kernel.
//
// Math: every feature is a polynomial in the token value t:
//   feats = [t^2, t, t+1, t^2, 2t+2, -1, t^2, 0, 2t+1, t^2, 2t+1, 0]
// so per output channel d:
//   out[tok][d] = A[d]*t^2 + B[d]*t + C[d]
//   A = w0+w3+w6+w9
//   B = w1+w2+2*(w4+w8+w10)
//   C = w2+2*w4-w5+w8+w10 + b
//
// dtype detection (int64 vs int32 tokens): all blocks probe the first 16 odd
// 32-bit words of the token buffer. For little-endian int64 values < 32000
// these are zero high-halves; for int32 they are random tokens
// (P(all zero) ~ 32000^-16). Reads stay within the first 32 int32 words,
// valid for either dtype (n_tok = 32768 >> 32).
// ---------------------------------------------------------------------------
__global__ __launch_bounds__(TPB)
void n2_embed_fused_kernel(const void* __restrict__ ntok_raw,
                           const float* __restrict__ W,
                           const float* __restrict__ b,
                           float4* __restrict__ out,
                           int n_tok) {
    __shared__ float s_t[TOK_PER_BLK];
    __shared__ int   s_is64;

    const int tid  = threadIdx.x;
    const int tok0 = blockIdx.x * TOK_PER_BLK;
    const int*  pi  = (const int*)ntok_raw;
    const int2* pi2 = (const int2*)ntok_raw;

    // ---- per-block dtype detection (warp 0, L2-broadcast probes) ----
    if (tid < 32) {
        int probe = (tid < 16) ? pi[2 * tid + 1] : 0;
        unsigned any = __ballot_sync(0xFFFFFFFFu, probe != 0);
        if (tid == 0) s_is64 = (any == 0) ? 1 : 0;
    }

    // ---- per-thread coefficient computation (independent of detection) ----
    // Thread's 4 channels: d = tid*4 .. tid*4+3. W rows are 12 floats each,
    // so the 48 floats are contiguous & 16B-aligned: 12 float4 loads.
    const int dbase = tid * 4;
    float4 wv[12];
    const float4* Wv = (const float4*)(W + (size_t)dbase * 12);
#pragma unroll
    for (int i = 0; i < 12; i++) wv[i] = Wv[i];
    const float4 bias = *(const float4*)(b + dbase);

    float4 A, B, C;
    {
        float a[4], bb[4], c[4];
#pragma unroll
        for (int c4 = 0; c4 < 4; c4++) {
            // channel c4 uses float4s [3*c4, 3*c4+2] = w0..w11
            float4 f0 = wv[3 * c4 + 0];   // w0 w1 w2 w3
            float4 f1 = wv[3 * c4 + 1];   // w4 w5 w6 w7
            float4 f2 = wv[3 * c4 + 2];   // w8 w9 w10 w11
            a[c4]  = f0.x + f0.w + f1.z + f2.y;                     // w0+w3+w6+w9
            bb[c4] = f0.y + f0.z + 2.0f * (f1.x + f2.x + f2.z);     // w1+w2+2(w4+w8+w10)
            c[c4]  = f0.z + 2.0f * f1.x - f1.y + f2.x + f2.z;       // + bias below
        }
        A = make_float4(a[0], a[1], a[2], a[3]);
        B = make_float4(bb[0], bb[1], bb[2], bb[3]);
        C = make_float4(c[0] + bias.x, c[1] + bias.y,
                        c[2] + bias.z, c[3] + bias.w);
    }

    __syncthreads();   // s_is64 visible

    // ---- load this block's tokens into shared ----
    if (tid < TOK_PER_BLK) {
        int idx = tok0 + tid;
        float t = 0.0f;
        if (idx < n_tok) {
            if (s_is64) {
                t = (float)pi2[idx].x;   // low word; tokens < 32000 fit
            } else {
                t = (float)pi[idx];
            }
        }
        s_t[tid] = t;
    }
    __syncthreads();

    // ---- main streaming loop: 2 FMAs + STG.128 per token per thread ----
    const int row_f4 = D_MODEL / 4;  // 256 float4 per token row
    float4* outp = out + (size_t)tok0 * row_f4 + tid;

#pragma unroll 8
    for (int k = 0; k < TOK_PER_BLK; k++) {
        int tok = tok0 + k;
        if (tok >= n_tok) break;
        float t = s_t[k];
        float4 o;
        o.x = fmaf(fmaf(A.x, t, B.x), t, C.x);
        o.y = fmaf(fmaf(A.y, t, B.y), t, C.y);
        o.z = fmaf(fmaf(A.z, t, B.z), t, C.z);
        o.w = fmaf(fmaf(A.w, t, B.w), t, C.w);
        outp[(size_t)k * row_f4] = o;
    }
}

extern "C" void kernel_launch(void* const* d_in, const int* in_sizes, int n_in,
                              void* d_out, int out_size) {
    const void*  ntok = d_in[0];                 // int64 or int32 tokens [B*S]
    const float* W    = (const float*)d_in[1];   // [D_MODEL, 12] row-major
    const float* b    = (const float*)d_in[2];   // [D_MODEL]
    float4* out = (float4*)d_out;

    int n_tok = in_sizes[0];                     // 32768
    int grid  = (n_tok + TOK_PER_BLK - 1) / TOK_PER_BLK;  // 512 blocks

    n2_embed_fused_kernel<<<grid, TPB>>>(ntok, W, b, out, n_tok);
}

// round 3
// speedup vs baseline: 1.4364x; 1.0403x over previous
#include <cuda_runtime.h>
#include <cstdint>

#define D_MODEL     1024
#define TPB         256     // each thread owns 4 contiguous channels
#define TOK_PER_BLK 32

// ---------------------------------------------------------------------------
// Single fused kernel.
//
// Math: every feature is a polynomial in the token value t:
//   feats = [t^2, t, t+1, t^2, 2t+2, -1, t^2, 0, 2t+1, t^2, 2t+1, 0]
// so per output channel d:
//   out[tok][d] = A[d]*t^2 + B[d]*t + C[d]
//   A = w0+w3+w6+w9
//   B = w1+w2+2*(w4+w8+w10)
//   C = w2+2*w4-w5+w8+w10 + b
//
// dtype detection (int64 vs int32 tokens): probe the first 16 odd 32-bit
// words. int64 little-endian values < 32000 -> all zero high-halves;
// int32 -> random tokens (P(all zero) ~ 32000^-16). Reads stay within the
// first 32 int32 words, valid for either dtype.
// ---------------------------------------------------------------------------
__global__ __launch_bounds__(TPB)
void n2_embed_fused_kernel(const void* __restrict__ ntok_raw,
                           const float* __restrict__ W,
                           const float* __restrict__ b,
                           float4* __restrict__ out,
                           int n_tok) {
    __shared__ float s_t[TOK_PER_BLK];
    __shared__ int   s_is64;

    const int tid  = threadIdx.x;
    const int tok0 = blockIdx.x * TOK_PER_BLK;
    const int*  pi  = (const int*)ntok_raw;
    const int2* pi2 = (const int2*)ntok_raw;

    // ---- per-block dtype detection (warp 0, L2-broadcast probes) ----
    if (tid < 32) {
        int probe = (tid < 16) ? pi[2 * tid + 1] : 0;
        unsigned any = __ballot_sync(0xFFFFFFFFu, probe != 0);
        if (tid == 0) s_is64 = (any == 0) ? 1 : 0;
    }

    // ---- per-thread coefficients: consume each W float4 immediately ----
    // Thread's 4 channels: d = tid*4 .. tid*4+3; 48 contiguous floats of W.
    const int dbase = tid * 4;
    const float4* Wv = (const float4*)(W + (size_t)dbase * 12);
    const float4 bias = *(const float4*)(b + dbase);

    float A[4], B[4], C[4];
#pragma unroll
    for (int c4 = 0; c4 < 4; c4++) {
        float4 f0 = Wv[3 * c4 + 0];   // w0 w1 w2 w3
        float4 f1 = Wv[3 * c4 + 1];   // w4 w5 w6 w7
        float4 f2 = Wv[3 * c4 + 2];   // w8 w9 w10 w11
        A[c4] = f0.x + f0.w + f1.z + f2.y;                   // w0+w3+w6+w9
        B[c4] = f0.y + f0.z + 2.0f * (f1.x + f2.x + f2.z);   // w1+w2+2(w4+w8+w10)
        C[c4] = f0.z + 2.0f * f1.x - f1.y + f2.x + f2.z;     // +bias below
    }
    C[0] += bias.x; C[1] += bias.y; C[2] += bias.z; C[3] += bias.w;

    __syncthreads();   // s_is64 visible

    // ---- load this block's tokens into shared ----
    if (tid < TOK_PER_BLK) {
        int idx = tok0 + tid;
        float t = 0.0f;
        if (idx < n_tok) {
            t = s_is64 ? (float)pi2[idx].x : (float)pi[idx];
        }
        s_t[tid] = t;
    }
    __syncthreads();

    // ---- main streaming loop: 2 FMAs + streaming STG.128 per token ----
    const int row_f4 = D_MODEL / 4;  // 256 float4 per token row
    float4* outp = out + (size_t)tok0 * row_f4 + tid;

    const int kmax = min(TOK_PER_BLK, n_tok - tok0);
#pragma unroll 4
    for (int k = 0; k < kmax; k++) {
        float t = s_t[k];
        float4 o;
        o.x = fmaf(fmaf(A[0], t, B[0]), t, C[0]);
        o.y = fmaf(fmaf(A[1], t, B[1]), t, C[1]);
        o.z = fmaf(fmaf(A[2], t, B[2]), t, C[2]);
        o.w = fmaf(fmaf(A[3], t, B[3]), t, C[3]);
        __stcs(outp + (size_t)k * row_f4, o);   // evict-first: output never re-read
    }
}

extern "C" void kernel_launch(void* const* d_in, const int* in_sizes, int n_in,
                              void* d_out, int out_size) {
    const void*  ntok = d_in[0];                 // int64 or int32 tokens [B*S]
    const float* W    = (const float*)d_in[1];   // [D_MODEL, 12] row-major
    const float* b    = (const float*)d_in[2];   // [D_MODEL]
    float4* out = (float4*)d_out;

    int n_tok = in_sizes[0];                     // 32768
    int grid  = (n_tok + TOK_PER_BLK - 1) / TOK_PER_BLK;  // 1024 blocks

    n2_embed_fused_kernel<<<grid, TPB>>>(ntok, W, b, out, n_tok);
}